// round 10
// baseline (speedup 1.0000x reference)
#include <cuda_runtime.h>

// Problem dims
#define BB 16
#define MM 128
#define NHD 256
#define EHD 128
#define HCD (NHD+EHD)    // 384 packed [Hn|He]
#define ROWS (BB*MM)     // 2048

typedef unsigned long long u64;

// Scratch
__device__ __align__(16) float d_aggE[ROWS*EHD];    // Σ_i A*E  [2048][128]
__device__ __align__(16) float d_sA[ROWS];          // colsum of A
__device__ __align__(16) float d_Nmap[ROWS*NHD];    // X @ Wv_w  [2048][256]
__device__ __align__(16) float d_Hc[ROWS*HCD];      // [Hn|He] [2048][384]
__device__ __align__(16) float d_partX[ROWS*NHD];   // relu(X)@Wu[384:640]

#define SMEM_FLOATS (2*16*68)   // 2176

// ---- packed f32x2 helpers ----
__device__ __forceinline__ u64 bcast2(float v) {
    u64 r; asm("mov.b64 %0, {%1, %1};" : "=l"(r) : "f"(v)); return r;
}
__device__ __forceinline__ void fmax2(u64 &d, u64 a, u64 b) {
    asm("fma.rn.f32x2 %0, %1, %2, %0;" : "+l"(d) : "l"(a), "l"(b));
}
__device__ __forceinline__ void unpack2(u64 v, float &lo, float &hi) {
    asm("mov.b64 {%0, %1}, %2;" : "=f"(lo), "=f"(hi) : "l"(v));
}

// ---------------------------------------------------------------------------
// Device GEMM: 64x64 tile, BK=16, 256 threads, 4x4 f32x2 micro-tile,
// register-prefetch double buffering.
// ---------------------------------------------------------------------------
template<bool TRANSA, bool RELUA, bool EPI>
__device__ __forceinline__
void devgemm(const float* __restrict__ Ab, int lda,
             const float* __restrict__ Bb, int ldb,
             float* __restrict__ Cb, int ldc, int K,
             const float* __restrict__ bias,
             const float* __restrict__ srow,
             int m0, int n0, float* sm) {
    float (*As)[68] = (float(*)[68])sm;
    float (*Bs)[68] = (float(*)[68])(sm + 16*68);

    const int tid = threadIdx.x;
    const int tx = tid & 15;
    const int ty = tid >> 4;

    u64 acc2[4][2] = {};

    float4 ra, rb;
    {
        if (TRANSA) {
            int kk = tid >> 4, c4 = tid & 15;
            ra = *(const float4*)&Ab[(long)kk * lda + m0 + c4 * 4];
        } else {
            int r = tid >> 2, c4 = tid & 3;
            ra = *(const float4*)&Ab[(long)(m0 + r) * lda + c4 * 4];
        }
        int kk = tid >> 4, c4 = tid & 15;
        rb = *(const float4*)&Bb[(long)kk * ldb + n0 + c4 * 4];
    }

    for (int k0 = 0; k0 < K; k0 += 16) {
        if (RELUA) {
            ra.x = fmaxf(ra.x, 0.f); ra.y = fmaxf(ra.y, 0.f);
            ra.z = fmaxf(ra.z, 0.f); ra.w = fmaxf(ra.w, 0.f);
        }
        if (TRANSA) {
            int kk = tid >> 4, c4 = tid & 15;
            *(float4*)&As[kk][c4 * 4] = ra;
        } else {
            int r = tid >> 2, c4 = tid & 3;
            As[c4 * 4 + 0][r] = ra.x;
            As[c4 * 4 + 1][r] = ra.y;
            As[c4 * 4 + 2][r] = ra.z;
            As[c4 * 4 + 3][r] = ra.w;
        }
        {
            int kk = tid >> 4, c4 = tid & 15;
            *(float4*)&Bs[kk][c4 * 4] = rb;
        }
        __syncthreads();

        int kn = k0 + 16;
        if (kn < K) {
            if (TRANSA) {
                int kk = tid >> 4, c4 = tid & 15;
                ra = *(const float4*)&Ab[(long)(kn + kk) * lda + m0 + c4 * 4];
            } else {
                int r = tid >> 2, c4 = tid & 3;
                ra = *(const float4*)&Ab[(long)(m0 + r) * lda + kn + c4 * 4];
            }
            int kk = tid >> 4, c4 = tid & 15;
            rb = *(const float4*)&Bb[(long)(kn + kk) * ldb + n0 + c4 * 4];
        }

        #pragma unroll
        for (int k = 0; k < 16; k++) {
            float4 a4 = *(const float4*)&As[k][ty * 4];
            ulonglong2 bv = *(const ulonglong2*)&Bs[k][tx * 4];
            u64 a0 = bcast2(a4.x), a1 = bcast2(a4.y);
            u64 a2 = bcast2(a4.z), a3 = bcast2(a4.w);
            fmax2(acc2[0][0], a0, bv.x); fmax2(acc2[0][1], a0, bv.y);
            fmax2(acc2[1][0], a1, bv.x); fmax2(acc2[1][1], a1, bv.y);
            fmax2(acc2[2][0], a2, bv.x); fmax2(acc2[2][1], a2, bv.y);
            fmax2(acc2[3][0], a3, bv.x); fmax2(acc2[3][1], a3, bv.y);
        }
        __syncthreads();
    }

    float4 bvv = make_float4(0.f, 0.f, 0.f, 0.f);
    if (EPI) bvv = *(const float4*)&bias[n0 + tx * 4];

    #pragma unroll
    for (int mm = 0; mm < 4; mm++) {
        int r = m0 + ty * 4 + mm;
        float4 v;
        unpack2(acc2[mm][0], v.x, v.y);
        unpack2(acc2[mm][1], v.z, v.w);
        if (EPI) {
            float s = srow[r];
            v.x = fmaxf(fmaf(s, bvv.x, v.x), 0.f);
            v.y = fmaxf(fmaf(s, bvv.y, v.y), 0.f);
            v.z = fmaxf(fmaf(s, bvv.z, v.z), 0.f);
            v.w = fmaxf(fmaf(s, bvv.w, v.w), 0.f);
        }
        *(float4*)&Cb[(long)r * ldc + n0 + tx * 4] = v;
    }
}

// ---------------------------------------------------------------------------
// E-stream for 4 j's per block; 2 warps per j split the i-range (keeps the
// launch's streaming-warp count at 2048 = full-E config despite half the j's).
// ---------------------------------------------------------------------------
__device__ __forceinline__
void ereduce4(const float* __restrict__ E, const float* __restrict__ A,
              int b, int j0, float* sm) {
    float (*As4)[MM] = (float(*)[MM])sm;          // [4][128]
    float (*agg)[132] = (float(*)[132])(sm + 4*MM); // [4][132]

    const int tid  = threadIdx.x;
    const int warp = tid >> 5;
    const int lane = tid & 31;
    const int jl   = warp >> 1;      // 0..3
    const int half = warp & 1;       // i half

    const float* Ab = A + (long)b * MM * MM;
    for (int idx = tid; idx < 4 * MM; idx += 256) {
        int jj = idx & 3;
        int i  = idx >> 2;
        As4[jj][i] = Ab[i * MM + j0 + jj];
    }
    __syncthreads();

    const int j = j0 + jl;
    const float4* Ep = (const float4*)E
        + ((long)(b * MM + half * 64) * MM + j) * (EHD / 4) + lane;
    const long istride = (long)MM * (EHD / 4);

    float4 acc = make_float4(0.f, 0.f, 0.f, 0.f);
    #pragma unroll 8
    for (int i = 0; i < 64; i++) {
        float a  = As4[jl][half * 64 + i];
        float4 v = Ep[(long)i * istride];
        acc.x = fmaf(a, v.x, acc.x);
        acc.y = fmaf(a, v.y, acc.y);
        acc.z = fmaf(a, v.z, acc.z);
        acc.w = fmaf(a, v.w, acc.w);
    }

    if (half == 0) *(float4*)&agg[jl][lane * 4] = acc;
    __syncthreads();
    if (half == 1) {
        float4 o = *(const float4*)&agg[jl][lane * 4];
        acc.x += o.x; acc.y += o.y; acc.z += o.z; acc.w += o.w;
        ((float4*)d_aggE)[(long)(b * MM + j) * (EHD / 4) + lane] = acc;
    }
}

// ---------------------------------------------------------------------------
// out tile: out[m0:m0+64, n0:n0+64] = (Hc @ Wu[0:384] + partX + Wu_b) * w
// ---------------------------------------------------------------------------
__device__ __forceinline__
void out_tile(const float* __restrict__ Wu_w, const float* __restrict__ Wu_b,
              const float* __restrict__ w, float* __restrict__ out,
              int m0, int n0, float* sm) {
    float (*As)[68] = (float(*)[68])sm;
    float (*Bs)[68] = (float(*)[68])(sm + 16*68);

    const int tid = threadIdx.x;
    const int tx = tid & 15;
    const int ty = tid >> 4;

    u64 acc2[4][2] = {};

    float4 ra, rb;
    {
        int r = tid >> 2, c4 = tid & 3;
        ra = *(const float4*)&d_Hc[(long)(m0 + r) * HCD + c4 * 4];
        int kk = tid >> 4, c4b = tid & 15;
        rb = *(const float4*)&Wu_w[(long)kk * NHD + n0 + c4b * 4];
    }

    for (int k0 = 0; k0 < HCD; k0 += 16) {
        {
            int r = tid >> 2, c4 = tid & 3;
            As[c4 * 4 + 0][r] = ra.x;
            As[c4 * 4 + 1][r] = ra.y;
            As[c4 * 4 + 2][r] = ra.z;
            As[c4 * 4 + 3][r] = ra.w;
            int kk = tid >> 4, c4b = tid & 15;
            *(float4*)&Bs[kk][c4b * 4] = rb;
        }
        __syncthreads();

        int kn = k0 + 16;
        if (kn < HCD) {
            int r = tid >> 2, c4 = tid & 3;
            ra = *(const float4*)&d_Hc[(long)(m0 + r) * HCD + kn + c4 * 4];
            int kk = tid >> 4, c4b = tid & 15;
            rb = *(const float4*)&Wu_w[(long)(kn + kk) * NHD + n0 + c4b * 4];
        }

        #pragma unroll
        for (int k = 0; k < 16; k++) {
            float4 a4 = *(const float4*)&As[k][ty * 4];
            ulonglong2 bv = *(const ulonglong2*)&Bs[k][tx * 4];
            u64 a0 = bcast2(a4.x), a1 = bcast2(a4.y);
            u64 a2 = bcast2(a4.z), a3 = bcast2(a4.w);
            fmax2(acc2[0][0], a0, bv.x); fmax2(acc2[0][1], a0, bv.y);
            fmax2(acc2[1][0], a1, bv.x); fmax2(acc2[1][1], a1, bv.y);
            fmax2(acc2[2][0], a2, bv.x); fmax2(acc2[2][1], a2, bv.y);
            fmax2(acc2[3][0], a3, bv.x); fmax2(acc2[3][1], a3, bv.y);
        }
        __syncthreads();
    }

    float4 bvv = *(const float4*)&Wu_b[n0 + tx * 4];
    #pragma unroll
    for (int mm = 0; mm < 4; mm++) {
        int r = m0 + ty * 4 + mm;
        float4 px = *(const float4*)&d_partX[(long)r * NHD + n0 + tx * 4];
        float wv = w[r];
        float4 v;
        unpack2(acc2[mm][0], v.x, v.y);
        unpack2(acc2[mm][1], v.z, v.w);
        v.x = (v.x + px.x + bvv.x) * wv;
        v.y = (v.y + px.y + bvv.y) * wv;
        v.z = (v.z + px.z + bvv.z) * wv;
        v.w = (v.w + px.w + bvv.w) * wv;
        *(float4*)&out[(long)r * NHD + n0 + tx * 4] = v;
    }
}

// ---------------------------------------------------------------------------
// L1 (528): stream j<64 [0,256) | Nmap [256,384) | partX [384,512) | sA [512,528)
// ---------------------------------------------------------------------------
__global__ __launch_bounds__(256, 4)
void l1_kernel(const float* __restrict__ E, const float* __restrict__ A,
               const float* __restrict__ X, const float* __restrict__ Wv_w,
               const float* __restrict__ Wu_w) {
    __shared__ float sm[SMEM_FLOATS];
    const int blk = blockIdx.x;

    if (blk < 256) {
        ereduce4(E, A, blk >> 4, (blk & 15) * 4, sm);
    } else if (blk < 384) {
        int idx = blk - 256;
        int mt = idx >> 2, nt = idx & 3;
        devgemm<false, false, false>(
            X, NHD, Wv_w, NHD, d_Nmap, NHD,
            NHD, nullptr, nullptr, mt * 64, nt * 64, sm);
    } else if (blk < 512) {
        int idx = blk - 384;
        int mt = idx >> 2, nt = idx & 3;
        devgemm<false, true, false>(
            X, NHD, Wu_w + (long)384 * NHD, NHD, d_partX, NHD,
            NHD, nullptr, nullptr, mt * 64, nt * 64, sm);
    } else {
        // sA for all: one block per batch
        int b = blk - 512;
        int t = threadIdx.x;
        if (t < MM) {
            const float* Ab = A + (long)b * MM * MM;
            float s = 0.f;
            #pragma unroll 8
            for (int i = 0; i < MM; i++) s += Ab[i * MM + t];
            d_sA[b * MM + t] = s;
        }
    }
}

// ---------------------------------------------------------------------------
// L2 (416): stream j>=64 [0,256) | Hn all [256,384) | He j<64 [384,416)
// ---------------------------------------------------------------------------
__global__ __launch_bounds__(256, 4)
void l2_kernel(const float* __restrict__ E, const float* __restrict__ A,
               const float* __restrict__ Wv_b,
               const float* __restrict__ We_w, const float* __restrict__ We_b) {
    __shared__ float sm[SMEM_FLOATS];
    const int blk = blockIdx.x;

    if (blk < 256) {
        ereduce4(E, A, blk >> 4, 64 + (blk & 15) * 4, sm);
    } else if (blk < 384) {
        // Hn[b] = relu(A[b]^T @ Nmap[b] + sA*Wv_b)  -> Hc[:,0:256]
        int idx = blk - 256;
        int b = idx >> 3, t = idx & 7;
        int mt = t >> 2, nt = t & 3;
        devgemm<true, false, true>(
            A + (long)b * MM * MM, MM,
            d_Nmap + (long)b * MM * NHD, NHD,
            d_Hc + (long)b * MM * HCD, HCD,
            MM, Wv_b, d_sA + b * MM, mt * 64, nt * 64, sm);
    } else {
        // He rows j<64 (per batch rows b*128 .. b*128+64)
        int idx = blk - 384;
        int b = idx >> 1, nt = idx & 1;
        devgemm<false, false, true>(
            d_aggE, EHD, We_w, EHD, d_Hc + NHD, HCD,
            EHD, We_b, d_sA, b * MM, nt * 64, sm);
    }
}

// ---------------------------------------------------------------------------
// L3 (96): He j>=64 [0,32) | out rows j<64 [32,96)
// ---------------------------------------------------------------------------
__global__ __launch_bounds__(256, 4)
void l3_kernel(const float* __restrict__ We_w, const float* __restrict__ We_b,
               const float* __restrict__ Wu_w, const float* __restrict__ Wu_b,
               const float* __restrict__ w, float* __restrict__ out) {
    __shared__ float sm[SMEM_FLOATS];
    const int blk = blockIdx.x;
    if (blk < 32) {
        int b = blk >> 1, nt = blk & 1;
        devgemm<false, false, true>(
            d_aggE, EHD, We_w, EHD, d_Hc + NHD, HCD,
            EHD, We_b, d_sA, b * MM + 64, nt * 64, sm);
    } else {
        int idx = blk - 32;
        int b = idx >> 2, nt = idx & 3;
        out_tile(Wu_w, Wu_b, w, out, b * MM, nt * 64, sm);
    }
}

// ---------------------------------------------------------------------------
// L4 (64): out rows j>=64
// ---------------------------------------------------------------------------
__global__ __launch_bounds__(256, 4)
void l4_kernel(const float* __restrict__ Wu_w, const float* __restrict__ Wu_b,
               const float* __restrict__ w, float* __restrict__ out) {
    __shared__ float sm[SMEM_FLOATS];
    const int blk = blockIdx.x;
    int b = blk >> 2, nt = blk & 3;
    out_tile(Wu_w, Wu_b, w, out, b * MM + 64, nt * 64, sm);
}

// ---------------------------------------------------------------------------
extern "C" void kernel_launch(void* const* d_in, const int* in_sizes, int n_in,
                              void* d_out, int out_size) {
    const float* X    = (const float*)d_in[0];   // [16,128,256]
    const float* E    = (const float*)d_in[1];   // [16,128,128,128]
    const float* A    = (const float*)d_in[2];   // [16,128,128]
    const float* w    = (const float*)d_in[3];   // [16,128,1]
    const float* Wv_w = (const float*)d_in[4];   // [256,256]
    const float* Wv_b = (const float*)d_in[5];   // [256]
    const float* We_w = (const float*)d_in[6];   // [128,128]
    const float* We_b = (const float*)d_in[7];   // [128]
    const float* Wu_w = (const float*)d_in[8];   // [640,256]
    const float* Wu_b = (const float*)d_in[9];   // [256]
    float* out = (float*)d_out;                  // [16,128,256]

    l1_kernel<<<528, 256>>>(E, A, X, Wv_w, Wu_w);
    l2_kernel<<<416, 256>>>(E, A, Wv_b, We_w, We_b);
    l3_kernel<<<96, 256>>>(We_w, We_b, Wu_w, Wu_b, w, out);
    l4_kernel<<<64, 256>>>(Wu_w, Wu_b, w, out);
}

// round 11
// speedup vs baseline: 1.0493x; 1.0493x over previous
#include <cuda_runtime.h>

// Problem dims
#define BB 16
#define MM 128
#define NHD 256
#define EHD 128
#define HCD (NHD+EHD)    // 384 packed [Hn|He]
#define ROWS (BB*MM)     // 2048
#define GRID 512

typedef unsigned long long u64;

// Scratch (static __device__, no allocations)
__device__ __align__(16) float d_aggE[ROWS*EHD];    // Σ_i A*E  [2048][128]
__device__ __align__(16) float d_sA[ROWS];          // colsum of A
__device__ __align__(16) float d_Nmap[ROWS*NHD];    // X @ Wv_w  [2048][256]
__device__ __align__(16) float d_Hc[ROWS*HCD];      // [Hn|He] [2048][384]
__device__ __align__(16) float d_partX[ROWS*NHD];   // relu(X)@Wu[384:640]

// grid barrier state (replay-safe: count returns to 0, gen monotonic)
__device__ unsigned g_count = 0;
__device__ unsigned g_gen = 0;

#define SMEM_FLOATS (2*16*68)   // 2176 floats

// ---- packed f32x2 helpers ----
__device__ __forceinline__ u64 bcast2(float v) {
    u64 r; asm("mov.b64 %0, {%1, %1};" : "=l"(r) : "f"(v)); return r;
}
__device__ __forceinline__ void fmax2(u64 &d, u64 a, u64 b) {
    asm("fma.rn.f32x2 %0, %1, %2, %0;" : "+l"(d) : "l"(a), "l"(b));
}
__device__ __forceinline__ void unpack2(u64 v, float &lo, float &hi) {
    asm("mov.b64 {%0, %1}, %2;" : "=f"(lo), "=f"(hi) : "l"(v));
}

// ---- software grid barrier (all GRID CTAs co-resident by launch_bounds) ----
__device__ __forceinline__ void grid_barrier() {
    __syncthreads();
    if (threadIdx.x == 0) {
        __threadfence();
        unsigned g = *(volatile unsigned*)&g_gen;
        if (atomicAdd(&g_count, 1) == GRID - 1) {
            *(volatile unsigned*)&g_count = 0;
            __threadfence();
            atomicAdd(&g_gen, 1);
        } else {
            while (*(volatile unsigned*)&g_gen == g) { __nanosleep(64); }
        }
        __threadfence();
    }
    __syncthreads();
}

// ---------------------------------------------------------------------------
// Device GEMM: 64x64 tile, BK=16, 256 threads, 4x4 f32x2 micro-tile,
// register-prefetch double buffering.
// ---------------------------------------------------------------------------
template<bool TRANSA, bool RELUA, bool EPI>
__device__ __forceinline__
void devgemm(const float* __restrict__ Ab, int lda,
             const float* __restrict__ Bb, int ldb,
             float* __restrict__ Cb, int ldc, int K,
             const float* __restrict__ bias,
             const float* __restrict__ srow,
             int m0, int n0, float* sm) {
    float (*As)[68] = (float(*)[68])sm;
    float (*Bs)[68] = (float(*)[68])(sm + 16*68);

    const int tid = threadIdx.x;
    const int tx = tid & 15;
    const int ty = tid >> 4;

    u64 acc2[4][2] = {};

    float4 ra, rb;
    {
        if (TRANSA) {
            int kk = tid >> 4, c4 = tid & 15;
            ra = *(const float4*)&Ab[(long)kk * lda + m0 + c4 * 4];
        } else {
            int r = tid >> 2, c4 = tid & 3;
            ra = *(const float4*)&Ab[(long)(m0 + r) * lda + c4 * 4];
        }
        int kk = tid >> 4, c4 = tid & 15;
        rb = *(const float4*)&Bb[(long)kk * ldb + n0 + c4 * 4];
    }

    for (int k0 = 0; k0 < K; k0 += 16) {
        if (RELUA) {
            ra.x = fmaxf(ra.x, 0.f); ra.y = fmaxf(ra.y, 0.f);
            ra.z = fmaxf(ra.z, 0.f); ra.w = fmaxf(ra.w, 0.f);
        }
        if (TRANSA) {
            int kk = tid >> 4, c4 = tid & 15;
            *(float4*)&As[kk][c4 * 4] = ra;
        } else {
            int r = tid >> 2, c4 = tid & 3;
            As[c4 * 4 + 0][r] = ra.x;
            As[c4 * 4 + 1][r] = ra.y;
            As[c4 * 4 + 2][r] = ra.z;
            As[c4 * 4 + 3][r] = ra.w;
        }
        {
            int kk = tid >> 4, c4 = tid & 15;
            *(float4*)&Bs[kk][c4 * 4] = rb;
        }
        __syncthreads();

        int kn = k0 + 16;
        if (kn < K) {
            if (TRANSA) {
                int kk = tid >> 4, c4 = tid & 15;
                ra = *(const float4*)&Ab[(long)(kn + kk) * lda + m0 + c4 * 4];
            } else {
                int r = tid >> 2, c4 = tid & 3;
                ra = *(const float4*)&Ab[(long)(m0 + r) * lda + kn + c4 * 4];
            }
            int kk = tid >> 4, c4 = tid & 15;
            rb = *(const float4*)&Bb[(long)(kn + kk) * ldb + n0 + c4 * 4];
        }

        #pragma unroll
        for (int k = 0; k < 16; k++) {
            float4 a4 = *(const float4*)&As[k][ty * 4];
            ulonglong2 bv = *(const ulonglong2*)&Bs[k][tx * 4];
            u64 a0 = bcast2(a4.x), a1 = bcast2(a4.y);
            u64 a2 = bcast2(a4.z), a3 = bcast2(a4.w);
            fmax2(acc2[0][0], a0, bv.x); fmax2(acc2[0][1], a0, bv.y);
            fmax2(acc2[1][0], a1, bv.x); fmax2(acc2[1][1], a1, bv.y);
            fmax2(acc2[2][0], a2, bv.x); fmax2(acc2[2][1], a2, bv.y);
            fmax2(acc2[3][0], a3, bv.x); fmax2(acc2[3][1], a3, bv.y);
        }
        __syncthreads();
    }

    float4 bvv = make_float4(0.f, 0.f, 0.f, 0.f);
    if (EPI) bvv = *(const float4*)&bias[n0 + tx * 4];

    #pragma unroll
    for (int mm = 0; mm < 4; mm++) {
        int r = m0 + ty * 4 + mm;
        float4 v;
        unpack2(acc2[mm][0], v.x, v.y);
        unpack2(acc2[mm][1], v.z, v.w);
        if (EPI) {
            float s = srow[r];
            v.x = fmaxf(fmaf(s, bvv.x, v.x), 0.f);
            v.y = fmaxf(fmaf(s, bvv.y, v.y), 0.f);
            v.z = fmaxf(fmaf(s, bvv.z, v.z), 0.f);
            v.w = fmaxf(fmaf(s, bvv.w, v.w), 0.f);
        }
        *(float4*)&Cb[(long)r * ldc + n0 + tx * 4] = v;
    }
}

// ---------------------------------------------------------------------------
// ereduce8: 8 j's per block, one warp each; also writes sA.
// ---------------------------------------------------------------------------
__device__ __forceinline__
void ereduce8(const float* __restrict__ E, const float* __restrict__ A,
              int b, int jg, float* sm) {
    float (*As8)[MM] = (float(*)[MM])sm;   // [8][128]
    const int tid = threadIdx.x;
    const int jl  = tid >> 5;
    const int lane = tid & 31;
    const int j0 = jg * 8;

    const float* Ab = A + (long)b * MM * MM;
    for (int idx = tid; idx < 8 * MM; idx += 256) {
        int jj = idx & 7;
        int i  = idx >> 3;
        As8[jj][i] = Ab[i * MM + j0 + jj];
    }
    __syncthreads();

    if (tid < 8) {
        float s = 0.f;
        #pragma unroll
        for (int i = 0; i < MM; i++) s += As8[tid][i];
        d_sA[b * MM + j0 + tid] = s;
    }

    const int j = j0 + jl;
    const float4* Ep = (const float4*)E + ((long)(b * MM) * MM + j) * (EHD / 4) + lane;
    const long istride = (long)MM * (EHD / 4);

    float4 acc = make_float4(0.f, 0.f, 0.f, 0.f);
    #pragma unroll 8
    for (int i = 0; i < MM; i++) {
        float a  = As8[jl][i];
        float4 v = Ep[(long)i * istride];
        acc.x = fmaf(a, v.x, acc.x);
        acc.y = fmaf(a, v.y, acc.y);
        acc.z = fmaf(a, v.z, acc.z);
        acc.w = fmaf(a, v.w, acc.w);
    }
    ((float4*)d_aggE)[(long)(b * MM + j) * (EHD / 4) + lane] = acc;
}

// ---------------------------------------------------------------------------
// out tile: out[m0:+64, n0:+64] = (Hc @ Wu[0:384] + partX + Wu_b) * w
// ---------------------------------------------------------------------------
__device__ __forceinline__
void out_tile(const float* __restrict__ Wu_w, const float* __restrict__ Wu_b,
              const float* __restrict__ w, float* __restrict__ out,
              int m0, int n0, float* sm) {
    float (*As)[68] = (float(*)[68])sm;
    float (*Bs)[68] = (float(*)[68])(sm + 16*68);

    const int tid = threadIdx.x;
    const int tx = tid & 15;
    const int ty = tid >> 4;

    u64 acc2[4][2] = {};

    float4 ra, rb;
    {
        int r = tid >> 2, c4 = tid & 3;
        ra = *(const float4*)&d_Hc[(long)(m0 + r) * HCD + c4 * 4];
        int kk = tid >> 4, c4b = tid & 15;
        rb = *(const float4*)&Wu_w[(long)kk * NHD + n0 + c4b * 4];
    }

    for (int k0 = 0; k0 < HCD; k0 += 16) {
        {
            int r = tid >> 2, c4 = tid & 3;
            As[c4 * 4 + 0][r] = ra.x;
            As[c4 * 4 + 1][r] = ra.y;
            As[c4 * 4 + 2][r] = ra.z;
            As[c4 * 4 + 3][r] = ra.w;
            int kk = tid >> 4, c4b = tid & 15;
            *(float4*)&Bs[kk][c4b * 4] = rb;
        }
        __syncthreads();

        int kn = k0 + 16;
        if (kn < HCD) {
            int r = tid >> 2, c4 = tid & 3;
            ra = *(const float4*)&d_Hc[(long)(m0 + r) * HCD + kn + c4 * 4];
            int kk = tid >> 4, c4b = tid & 15;
            rb = *(const float4*)&Wu_w[(long)(kn + kk) * NHD + n0 + c4b * 4];
        }

        #pragma unroll
        for (int k = 0; k < 16; k++) {
            float4 a4 = *(const float4*)&As[k][ty * 4];
            ulonglong2 bv = *(const ulonglong2*)&Bs[k][tx * 4];
            u64 a0 = bcast2(a4.x), a1 = bcast2(a4.y);
            u64 a2 = bcast2(a4.z), a3 = bcast2(a4.w);
            fmax2(acc2[0][0], a0, bv.x); fmax2(acc2[0][1], a0, bv.y);
            fmax2(acc2[1][0], a1, bv.x); fmax2(acc2[1][1], a1, bv.y);
            fmax2(acc2[2][0], a2, bv.x); fmax2(acc2[2][1], a2, bv.y);
            fmax2(acc2[3][0], a3, bv.x); fmax2(acc2[3][1], a3, bv.y);
        }
        __syncthreads();
    }

    float4 bvv = *(const float4*)&Wu_b[n0 + tx * 4];
    #pragma unroll
    for (int mm = 0; mm < 4; mm++) {
        int r = m0 + ty * 4 + mm;
        float4 px = *(const float4*)&d_partX[(long)r * NHD + n0 + tx * 4];
        float wv = w[r];
        float4 v;
        unpack2(acc2[mm][0], v.x, v.y);
        unpack2(acc2[mm][1], v.z, v.w);
        v.x = (v.x + px.x + bvv.x) * wv;
        v.y = (v.y + px.y + bvv.y) * wv;
        v.z = (v.z + px.z + bvv.z) * wv;
        v.w = (v.w + px.w + bvv.w) * wv;
        *(float4*)&out[(long)r * NHD + n0 + tx * 4] = v;
    }
}

// ---------------------------------------------------------------------------
// Mega kernel: 512 co-resident CTAs, 3 stages, 2 grid barriers.
// ---------------------------------------------------------------------------
__global__ __launch_bounds__(256, 4)
void mega_kernel(const float* __restrict__ E, const float* __restrict__ A,
                 const float* __restrict__ X,
                 const float* __restrict__ Wv_w, const float* __restrict__ Wv_b,
                 const float* __restrict__ We_w, const float* __restrict__ We_b,
                 const float* __restrict__ Wu_w, const float* __restrict__ Wu_b,
                 const float* __restrict__ w, float* __restrict__ out) {
    __shared__ float sm[SMEM_FLOATS];
    const int blk = blockIdx.x;

    // ---- Stage A: ereduce+sA | Nmap | partX ----
    if (blk < 256) {
        ereduce8(E, A, blk >> 4, blk & 15, sm);
    } else if (blk < 384) {
        int idx = blk - 256;
        int mt = idx >> 2, nt = idx & 3;
        devgemm<false, false, false>(
            X, NHD, Wv_w, NHD, d_Nmap, NHD,
            NHD, nullptr, nullptr, mt * 64, nt * 64, sm);
    } else {
        int idx = blk - 384;
        int mt = idx >> 2, nt = idx & 3;
        devgemm<false, true, false>(
            X, NHD, Wu_w + (long)384 * NHD, NHD, d_partX, NHD,
            NHD, nullptr, nullptr, mt * 64, nt * 64, sm);
    }

    grid_barrier();

    // ---- Stage B: Hn (128) | He (64) ----
    if (blk < 128) {
        int b = blk >> 3, t = blk & 7;
        int mt = t >> 2, nt = t & 3;
        devgemm<true, false, true>(
            A + (long)b * MM * MM, MM,
            d_Nmap + (long)b * MM * NHD, NHD,
            d_Hc + (long)b * MM * HCD, HCD,
            MM, Wv_b, d_sA + b * MM, mt * 64, nt * 64, sm);
    } else if (blk < 192) {
        int idx = blk - 128;
        int mt = idx >> 1, nt = idx & 1;
        devgemm<false, false, true>(
            d_aggE, EHD, We_w, EHD, d_Hc + NHD, HCD,
            EHD, We_b, d_sA, mt * 64, nt * 64, sm);
    }

    grid_barrier();

    // ---- Stage C: out (128) ----
    if (blk < 128) {
        int mt = blk >> 2, nt = blk & 3;
        out_tile(Wu_w, Wu_b, w, out, mt * 64, nt * 64, sm);
    }
}

// ---------------------------------------------------------------------------
extern "C" void kernel_launch(void* const* d_in, const int* in_sizes, int n_in,
                              void* d_out, int out_size) {
    const float* X    = (const float*)d_in[0];   // [16,128,256]
    const float* E    = (const float*)d_in[1];   // [16,128,128,128]
    const float* A    = (const float*)d_in[2];   // [16,128,128]
    const float* w    = (const float*)d_in[3];   // [16,128,1]
    const float* Wv_w = (const float*)d_in[4];   // [256,256]
    const float* Wv_b = (const float*)d_in[5];   // [256]
    const float* We_w = (const float*)d_in[6];   // [128,128]
    const float* We_b = (const float*)d_in[7];   // [128]
    const float* Wu_w = (const float*)d_in[8];   // [640,256]
    const float* Wu_b = (const float*)d_in[9];   // [256]
    float* out = (float*)d_out;                  // [16,128,256]

    mega_kernel<<<GRID, 256>>>(E, A, X, Wv_w, Wv_b, We_w, We_b,
                               Wu_w, Wu_b, w, out);
}

// round 12
// speedup vs baseline: 1.0804x; 1.0296x over previous
#include <cuda_runtime.h>

// Problem dims
#define BB 16
#define MM 128
#define NHD 256
#define EHD 128
#define HCD (NHD+EHD)    // 384 packed [Hn|He]
#define ROWS (BB*MM)     // 2048

typedef unsigned long long u64;

// Scratch (static __device__, no allocations)
__device__ __align__(16) float d_aggE[ROWS*EHD];    // Σ_i A*E  [2048][128]
__device__ __align__(16) float d_sA[ROWS];          // colsum of A
__device__ __align__(16) float d_AX[ROWS*NHD];      // A^T @ X  [2048][256]
__device__ __align__(16) float d_Hc[ROWS*HCD];      // [Hn|He] [2048][384]
__device__ __align__(16) float d_partX[ROWS*NHD];   // relu(X)@Wu[384:640]

#define SMEM_FLOATS (2*16*68)   // 2176 floats

// ---- packed f32x2 helpers ----
__device__ __forceinline__ u64 bcast2(float v) {
    u64 r; asm("mov.b64 %0, {%1, %1};" : "=l"(r) : "f"(v)); return r;
}
__device__ __forceinline__ void fmax2(u64 &d, u64 a, u64 b) {
    asm("fma.rn.f32x2 %0, %1, %2, %0;" : "+l"(d) : "l"(a), "l"(b));
}
__device__ __forceinline__ void unpack2(u64 v, float &lo, float &hi) {
    asm("mov.b64 {%0, %1}, %2;" : "=f"(lo), "=f"(hi) : "l"(v));
}

// ---------------------------------------------------------------------------
// 256-thread GEMM (phase1 only — hides under the HBM stream): 64x64 tile,
// BK=16, 4x4 f32x2 micro-tile, reg-prefetch double buffering.
// ---------------------------------------------------------------------------
template<bool TRANSA, bool RELUA>
__device__ __forceinline__
void devgemm(const float* __restrict__ Ab, int lda,
             const float* __restrict__ Bb, int ldb,
             float* __restrict__ Cb, int ldc, int K,
             int m0, int n0, float* sm) {
    float (*As)[68] = (float(*)[68])sm;
    float (*Bs)[68] = (float(*)[68])(sm + 16*68);

    const int tid = threadIdx.x;
    const int tx = tid & 15;
    const int ty = tid >> 4;

    u64 acc2[4][2] = {};

    float4 ra, rb;
    {
        if (TRANSA) {
            int kk = tid >> 4, c4 = tid & 15;
            ra = *(const float4*)&Ab[(long)kk * lda + m0 + c4 * 4];
        } else {
            int r = tid >> 2, c4 = tid & 3;
            ra = *(const float4*)&Ab[(long)(m0 + r) * lda + c4 * 4];
        }
        int kk = tid >> 4, c4 = tid & 15;
        rb = *(const float4*)&Bb[(long)kk * ldb + n0 + c4 * 4];
    }

    for (int k0 = 0; k0 < K; k0 += 16) {
        if (RELUA) {
            ra.x = fmaxf(ra.x, 0.f); ra.y = fmaxf(ra.y, 0.f);
            ra.z = fmaxf(ra.z, 0.f); ra.w = fmaxf(ra.w, 0.f);
        }
        if (TRANSA) {
            int kk = tid >> 4, c4 = tid & 15;
            *(float4*)&As[kk][c4 * 4] = ra;
        } else {
            int r = tid >> 2, c4 = tid & 3;
            As[c4 * 4 + 0][r] = ra.x;
            As[c4 * 4 + 1][r] = ra.y;
            As[c4 * 4 + 2][r] = ra.z;
            As[c4 * 4 + 3][r] = ra.w;
        }
        {
            int kk = tid >> 4, c4 = tid & 15;
            *(float4*)&Bs[kk][c4 * 4] = rb;
        }
        __syncthreads();

        int kn = k0 + 16;
        if (kn < K) {
            if (TRANSA) {
                int kk = tid >> 4, c4 = tid & 15;
                ra = *(const float4*)&Ab[(long)(kn + kk) * lda + m0 + c4 * 4];
            } else {
                int r = tid >> 2, c4 = tid & 3;
                ra = *(const float4*)&Ab[(long)(m0 + r) * lda + kn + c4 * 4];
            }
            int kk = tid >> 4, c4 = tid & 15;
            rb = *(const float4*)&Bb[(long)(kn + kk) * ldb + n0 + c4 * 4];
        }

        #pragma unroll
        for (int k = 0; k < 16; k++) {
            float4 a4 = *(const float4*)&As[k][ty * 4];
            ulonglong2 bv = *(const ulonglong2*)&Bs[k][tx * 4];
            u64 a0 = bcast2(a4.x), a1 = bcast2(a4.y);
            u64 a2 = bcast2(a4.z), a3 = bcast2(a4.w);
            fmax2(acc2[0][0], a0, bv.x); fmax2(acc2[0][1], a0, bv.y);
            fmax2(acc2[1][0], a1, bv.x); fmax2(acc2[1][1], a1, bv.y);
            fmax2(acc2[2][0], a2, bv.x); fmax2(acc2[2][1], a2, bv.y);
            fmax2(acc2[3][0], a3, bv.x); fmax2(acc2[3][1], a3, bv.y);
        }
        __syncthreads();
    }

    #pragma unroll
    for (int mm = 0; mm < 4; mm++) {
        int r = m0 + ty * 4 + mm;
        float4 v;
        unpack2(acc2[mm][0], v.x, v.y);
        unpack2(acc2[mm][1], v.z, v.w);
        *(float4*)&Cb[(long)r * ldc + n0 + tx * 4] = v;
    }
}

// ---------------------------------------------------------------------------
// 128-thread GEMM: 64x64 tile, BK=16, 8x4 f32x2 micro-tile (0.75 B/FLOP on
// the smem crossbar vs 1.0 for 4x4). Reg-prefetch double buffering.
// OUTMODE=false: C = relu(acc + srow[r]*bias[n])    (Hn/He)
// OUTMODE=true : C = (acc + partX + bias[n]) * w[r] (final output)
// ---------------------------------------------------------------------------
template<bool OUTMODE>
__device__ __forceinline__
void gemm128(const float* __restrict__ Ab, int lda,
             const float* __restrict__ Bb, int ldb,
             float* __restrict__ Cb, int ldc, int K,
             const float* __restrict__ bias,
             const float* __restrict__ srow,     // sA (EPI) or w (OUT)
             const float* __restrict__ px,       // partX base (OUT only)
             int m0, int n0, float* sm) {
    float (*As)[68] = (float(*)[68])sm;
    float (*Bs)[68] = (float(*)[68])(sm + 16*68);

    const int tid = threadIdx.x;
    const int tx = tid & 15;      // n group: tx*4
    const int ty = tid >> 4;      // m group: ty*8

    u64 acc2[8][2] = {};

    // A loader: thread t -> row r = t&63, k-half kh = t>>6 (2 float4 each)
    const int lr  = tid & 63;
    const int lkh = (tid >> 6) * 8;    // k offset 0 or 8
    // B loader: kk = t>>3 (16 rows), c8 = (t&7)*8 (2 float4 each)
    const int lkk = tid >> 3;
    const int lc8 = (tid & 7) * 8;

    float4 ra0, ra1, rb0, rb1;
    {
        const float* ap = &Ab[(long)(m0 + lr) * lda + lkh];
        ra0 = *(const float4*)ap;
        ra1 = *(const float4*)(ap + 4);
        const float* bp = &Bb[(long)lkk * ldb + n0 + lc8];
        rb0 = *(const float4*)bp;
        rb1 = *(const float4*)(bp + 4);
    }

    for (int k0 = 0; k0 < K; k0 += 16) {
        // store prefetched tiles (A transposed into As[k][m])
        As[lkh + 0][lr] = ra0.x;
        As[lkh + 1][lr] = ra0.y;
        As[lkh + 2][lr] = ra0.z;
        As[lkh + 3][lr] = ra0.w;
        As[lkh + 4][lr] = ra1.x;
        As[lkh + 5][lr] = ra1.y;
        As[lkh + 6][lr] = ra1.z;
        As[lkh + 7][lr] = ra1.w;
        *(float4*)&Bs[lkk][lc8]     = rb0;
        *(float4*)&Bs[lkk][lc8 + 4] = rb1;
        __syncthreads();

        int kn = k0 + 16;
        if (kn < K) {
            const float* ap = &Ab[(long)(m0 + lr) * lda + kn + lkh];
            ra0 = *(const float4*)ap;
            ra1 = *(const float4*)(ap + 4);
            const float* bp = &Bb[(long)(kn + lkk) * ldb + n0 + lc8];
            rb0 = *(const float4*)bp;
            rb1 = *(const float4*)(bp + 4);
        }

        #pragma unroll
        for (int k = 0; k < 16; k++) {
            float4 a0 = *(const float4*)&As[k][ty * 8];
            float4 a1 = *(const float4*)&As[k][ty * 8 + 4];
            ulonglong2 bv = *(const ulonglong2*)&Bs[k][tx * 4];
            u64 p0 = bcast2(a0.x), p1 = bcast2(a0.y);
            u64 p2 = bcast2(a0.z), p3 = bcast2(a0.w);
            u64 p4 = bcast2(a1.x), p5 = bcast2(a1.y);
            u64 p6 = bcast2(a1.z), p7 = bcast2(a1.w);
            fmax2(acc2[0][0], p0, bv.x); fmax2(acc2[0][1], p0, bv.y);
            fmax2(acc2[1][0], p1, bv.x); fmax2(acc2[1][1], p1, bv.y);
            fmax2(acc2[2][0], p2, bv.x); fmax2(acc2[2][1], p2, bv.y);
            fmax2(acc2[3][0], p3, bv.x); fmax2(acc2[3][1], p3, bv.y);
            fmax2(acc2[4][0], p4, bv.x); fmax2(acc2[4][1], p4, bv.y);
            fmax2(acc2[5][0], p5, bv.x); fmax2(acc2[5][1], p5, bv.y);
            fmax2(acc2[6][0], p6, bv.x); fmax2(acc2[6][1], p6, bv.y);
            fmax2(acc2[7][0], p7, bv.x); fmax2(acc2[7][1], p7, bv.y);
        }
        __syncthreads();
    }

    float4 bvv = *(const float4*)&bias[n0 + tx * 4];

    #pragma unroll
    for (int mm = 0; mm < 8; mm++) {
        int r = m0 + ty * 8 + mm;
        float4 v;
        unpack2(acc2[mm][0], v.x, v.y);
        unpack2(acc2[mm][1], v.z, v.w);
        if (OUTMODE) {
            float4 p = *(const float4*)&px[(long)r * NHD + n0 + tx * 4];
            float wv = srow[r];
            v.x = (v.x + p.x + bvv.x) * wv;
            v.y = (v.y + p.y + bvv.y) * wv;
            v.z = (v.z + p.z + bvv.z) * wv;
            v.w = (v.w + p.w + bvv.w) * wv;
        } else {
            float s = srow[r];
            v.x = fmaxf(fmaf(s, bvv.x, v.x), 0.f);
            v.y = fmaxf(fmaf(s, bvv.y, v.y), 0.f);
            v.z = fmaxf(fmaf(s, bvv.z, v.z), 0.f);
            v.w = fmaxf(fmaf(s, bvv.w, v.w), 0.f);
        }
        *(float4*)&Cb[(long)r * ldc + n0 + tx * 4] = v;
    }
}

// ---------------------------------------------------------------------------
// ereduce8: 8 j's per block, one warp each; also writes sA.
// ---------------------------------------------------------------------------
__device__ __forceinline__
void ereduce8(const float* __restrict__ E, const float* __restrict__ A,
              int b, int jg, float* sm) {
    float (*As8)[MM] = (float(*)[MM])sm;   // [8][128]
    const int tid = threadIdx.x;
    const int jl  = tid >> 5;
    const int lane = tid & 31;
    const int j0 = jg * 8;

    const float* Ab = A + (long)b * MM * MM;
    for (int idx = tid; idx < 8 * MM; idx += 256) {
        int jj = idx & 7;
        int i  = idx >> 3;
        As8[jj][i] = Ab[i * MM + j0 + jj];
    }
    __syncthreads();

    if (tid < 8) {
        float s = 0.f;
        #pragma unroll
        for (int i = 0; i < MM; i++) s += As8[tid][i];
        d_sA[b * MM + j0 + tid] = s;
    }

    const int j = j0 + jl;
    const float4* Ep = (const float4*)E + ((long)(b * MM) * MM + j) * (EHD / 4) + lane;
    const long istride = (long)MM * (EHD / 4);

    float4 acc = make_float4(0.f, 0.f, 0.f, 0.f);
    #pragma unroll 8
    for (int i = 0; i < MM; i++) {
        float a  = As8[jl][i];
        float4 v = Ep[(long)i * istride];
        acc.x = fmaf(a, v.x, acc.x);
        acc.y = fmaf(a, v.y, acc.y);
        acc.z = fmaf(a, v.z, acc.z);
        acc.w = fmaf(a, v.w, acc.w);
    }
    ((float4*)d_aggE)[(long)(b * MM + j) * (EHD / 4) + lane] = acc;
}

// ---------------------------------------------------------------------------
// Phase 1 (512 blocks, 256 thr): ereduce [0,256) | AX [256,384) | partX [384,512)
// ---------------------------------------------------------------------------
__global__ __launch_bounds__(256, 4)
void phase1_kernel(const float* __restrict__ E, const float* __restrict__ A,
                   const float* __restrict__ X, const float* __restrict__ Wu_w) {
    __shared__ float sm[SMEM_FLOATS];
    const int blk = blockIdx.x;

    if (blk < 256) {
        ereduce8(E, A, blk >> 4, blk & 15, sm);
    } else if (blk < 384) {
        // AX[b] = A[b]^T @ X[b]
        int idx = blk - 256;
        int b = idx >> 3, t = idx & 7;
        int mt = t >> 2, nt = t & 3;
        devgemm<true, false>(
            A + (long)b * MM * MM, MM,
            X + (long)b * MM * NHD, NHD,
            d_AX + (long)b * MM * NHD, NHD,
            MM, mt * 64, nt * 64, sm);
    } else {
        // partX = relu(X) @ Wu_w[384:640, :]   (K=256)
        int idx = blk - 384;
        int mt = idx >> 2, nt = idx & 3;
        devgemm<false, true>(
            X, NHD, Wu_w + (long)384 * NHD, NHD, d_partX, NHD,
            NHD, mt * 64, nt * 64, sm);
    }
}

// ---------------------------------------------------------------------------
// Phase 2 (192 blocks, 128 thr): Hn [0,128) | He [128,192)
// ---------------------------------------------------------------------------
__global__ __launch_bounds__(128, 4)
void phase2_kernel(const float* __restrict__ Wv_w, const float* __restrict__ Wv_b,
                   const float* __restrict__ We_w, const float* __restrict__ We_b) {
    __shared__ float sm[SMEM_FLOATS];
    const int blk = blockIdx.x;
    if (blk < 128) {
        int mt = blk >> 2, nt = blk & 3;
        gemm128<false>(
            d_AX, NHD, Wv_w, NHD, d_Hc, HCD,
            NHD, Wv_b, d_sA, nullptr, mt * 64, nt * 64, sm);
    } else {
        int idx = blk - 128;
        int mt = idx >> 1, nt = idx & 1;
        gemm128<false>(
            d_aggE, EHD, We_w, EHD, d_Hc + NHD, HCD,
            EHD, We_b, d_sA, nullptr, mt * 64, nt * 64, sm);
    }
}

// ---------------------------------------------------------------------------
// Output kernel (128 blocks, 128 thr): out = (Hc@Wu[0:384] + partX + Wu_b)*w
// ---------------------------------------------------------------------------
__global__ __launch_bounds__(128, 4)
void out_kernel(const float* __restrict__ Wu_w, const float* __restrict__ Wu_b,
                const float* __restrict__ w, float* __restrict__ out) {
    __shared__ float sm[SMEM_FLOATS];
    const int mt = blockIdx.x;
    const int nt = blockIdx.y;
    gemm128<true>(
        d_Hc, HCD, Wu_w, NHD, out, NHD,
        HCD, Wu_b, w, d_partX, mt * 64, nt * 64, sm);
}

// ---------------------------------------------------------------------------
extern "C" void kernel_launch(void* const* d_in, const int* in_sizes, int n_in,
                              void* d_out, int out_size) {
    const float* X    = (const float*)d_in[0];   // [16,128,256]
    const float* E    = (const float*)d_in[1];   // [16,128,128,128]
    const float* A    = (const float*)d_in[2];   // [16,128,128]
    const float* w    = (const float*)d_in[3];   // [16,128,1]
    const float* Wv_w = (const float*)d_in[4];   // [256,256]
    const float* Wv_b = (const float*)d_in[5];   // [256]
    const float* We_w = (const float*)d_in[6];   // [128,128]
    const float* We_b = (const float*)d_in[7];   // [128]
    const float* Wu_w = (const float*)d_in[8];   // [640,256]
    const float* Wu_b = (const float*)d_in[9];   // [256]
    float* out = (float*)d_out;                  // [16,128,256]

    // Phase 1: ereduce + AX + partX (GEMMs hide under the 134MB HBM stream)
    phase1_kernel<<<512, 256>>>(E, A, X, Wu_w);

    // Phase 2: Hn | He  (8x4 micro-tile, smem-BW balanced)
    phase2_kernel<<<192, 128>>>(Wv_w, Wv_b, We_w, We_b);

    // Phase 3: fused final GEMM + partial add + bias + w scale
    out_kernel<<<dim3(ROWS / 64, NHD / 64), 128>>>(Wu_w, Wu_b, w, out);
}